// round 16
// baseline (speedup 1.0000x reference)
#include <cuda_runtime.h>
#include <math.h>
#include <string.h>

typedef unsigned long long ull;
typedef unsigned short us;

#define GSTR 256            // gathered row stride (floats)
#define YSTR 264            // y row stride (floats)
#define UNION_FLOATS (32*YSTR)   // 8448 floats = 33792 B  (>= 32*GSTR)
#define MAX_ITEMS 336
#define MAX_TERMS 1568      // term table bound (actual real ~1.4K + even-pad <= 1556)

// 16-byte item record (LDS.128-friendly)
struct __align__(16) DItem { int outConst; us bvStride, termStart, termCount, yAdd; us pad; };

__device__ ull   gTerms[MAX_TERMS];     // term = {float c (low 32), int y (high 32)}
__device__ DItem gItems[MAX_ITEMS];

// union(sG,sY) 33792 + sK 4096 + sT 12544 + sItems 5376 = 55808 B -> 4 CTAs/SM (223.2 KB)
#define SMEM_BYTES (UNION_FLOATS*4 + 32*32*4 + MAX_TERMS*8 + MAX_ITEMS*16)

// ===================== device kernel =====================

__global__ void __launch_bounds__(256, 4) shconv_kernel(
    int nItems,
    const float* __restrict__ x0, const float* __restrict__ x1,
    const float* __restrict__ x2, const float* __restrict__ x3,
    const int*  __restrict__ pidx, const float* __restrict__ kern,
    float* __restrict__ out)
{
    extern __shared__ float smem[];
    float* sG  = smem;                      // [32][GSTR]  (phase 1-2)
    float* sY  = smem;                      // [32][YSTR]  (aliases sG after barrier)
    float* sK  = smem + UNION_FLOATS;       // [32][32]    K, rows 30,31 zero-padded
    ull*   sT  = (ull*)(sK + 1024);         // [MAX_TERMS] term table
    DItem* sIt = (DItem*)(sT + MAX_TERMS);  // [MAX_ITEMS] items

    const int bv   = blockIdx.x;
    const int t    = threadIdx.x;
    const int lane = t & 31, w = t >> 5;

    // ---- Phase 0a: copy term + item tables into smem (coalesced, L2-hot) ----
    for (int i = t; i < MAX_TERMS; i += 256)
        sT[i] = gTerms[i];
    {
        const ulonglong2* gi = (const ulonglong2*)gItems;
        ulonglong2* si = (ulonglong2*)sIt;
        for (int i = t; i < MAX_ITEMS; i += 256) si[i] = gi[i];
    }

    // ---- Phase 0b: load K[32 patches][30 rows], pad rows to 32 ----
    const float* kb = kern + (size_t)bv * (32*30);
    for (int e = t; e < 1024; e += 256) {
        int p = e >> 5, row = e & 31;
        sK[e] = (row < 30) ? __ldg(kb + p*30 + row) : 0.f;
    }

    // ---- Phase 1: gather G[32][256] via cp.async (L2 -> smem, no L1/register trip) ----
    const int* pb = pidx + (size_t)bv * 64;
    #pragma unroll
    for (int pi = 0; pi < 4; pi++) {
        int p  = w + pi*8;
        int b2 = __ldg(pb + 2*p);
        int n  = __ldg(pb + 2*p + 1);
        size_t bn = (size_t)b2 * 4096 + (size_t)n;
        #pragma unroll
        for (int qq = 0; qq < 2; qq++) {
            int q = lane + qq*32;    // 64 float4 chunks per patch row
            const float* src;
            if (q < 4)       src = x0 + bn*16  + q*4;
            else if (q < 16) src = x1 + bn*48  + (q-4)*4;
            else if (q < 36) src = x2 + bn*80  + (q-16)*4;
            else             src = x3 + bn*112 + (q-36)*4;
            unsigned daddr = (unsigned)__cvta_generic_to_shared(&sG[p*GSTR + q*4]);
            asm volatile("cp.async.cg.shared.global [%0], [%1], 16;\n"
                         :: "r"(daddr), "l"(src));
        }
    }
    asm volatile("cp.async.commit_group;\n");
    asm volatile("cp.async.wait_group 0;\n");
    __syncthreads();

    // ---- Phase 2: y[30][256] = K^T(30x32) @ G(32x256), 8 rows x 64 pairs per warp ----
    {
        const int rg = w >> 1;          // row group: rows rg*8 .. rg*8+7 (rows padded to 32)
        const int ph = w & 1;           // pair half
        const int col = (ph*64 + lane)*2;   // float column of first pair
        ull acc[8][2];
        #pragma unroll
        for (int i = 0; i < 8; i++) { acc[i][0] = 0ull; acc[i][1] = 0ull; }

        #pragma unroll 2
        for (int p = 0; p < 32; p++) {
            const float* gr = sG + p*GSTR + col;
            ull g0 = *(const ull*)(gr);
            ull g1 = *(const ull*)(gr + 64);
            float4 ka = *(const float4*)&sK[p*32 + rg*8];       // broadcast LDS.128
            float4 kc = *(const float4*)&sK[p*32 + rg*8 + 4];   // broadcast LDS.128
            ull kd[8];
            asm("mov.b64 %0, {%1,%1};" : "=l"(kd[0]) : "r"(__float_as_uint(ka.x)));
            asm("mov.b64 %0, {%1,%1};" : "=l"(kd[1]) : "r"(__float_as_uint(ka.y)));
            asm("mov.b64 %0, {%1,%1};" : "=l"(kd[2]) : "r"(__float_as_uint(ka.z)));
            asm("mov.b64 %0, {%1,%1};" : "=l"(kd[3]) : "r"(__float_as_uint(ka.w)));
            asm("mov.b64 %0, {%1,%1};" : "=l"(kd[4]) : "r"(__float_as_uint(kc.x)));
            asm("mov.b64 %0, {%1,%1};" : "=l"(kd[5]) : "r"(__float_as_uint(kc.y)));
            asm("mov.b64 %0, {%1,%1};" : "=l"(kd[6]) : "r"(__float_as_uint(kc.z)));
            asm("mov.b64 %0, {%1,%1};" : "=l"(kd[7]) : "r"(__float_as_uint(kc.w)));
            #pragma unroll
            for (int i = 0; i < 8; i++) {
                asm("fma.rn.f32x2 %0, %1, %2, %0;" : "+l"(acc[i][0]) : "l"(kd[i]), "l"(g0));
                asm("fma.rn.f32x2 %0, %1, %2, %0;" : "+l"(acc[i][1]) : "l"(kd[i]), "l"(g1));
            }
        }
        // all warps finished reading sG -> safe to overwrite the union region with y
        __syncthreads();
        #pragma unroll
        for (int i = 0; i < 8; i++) {
            int row = rg*8 + i;
            *(ull*)&sY[row*YSTR + col]      = acc[i][0];
            *(ull*)&sY[row*YSTR + col + 64] = acc[i][1];
        }
    }
    __syncthreads();

    // ---- Phase 3: CG recombination + direct copies, 4 floats/lane, 2 terms/iter ----
    // Term lists are even-length and 16B-aligned (host pads with zero-coeff terms).
    {
        const int c4  = (t & 3) * 4;    // channels c4..c4+3 (16 per item, 4 lanes/item)
        const int grp = t >> 2;         // 64 item-groups
        for (int it = grp; it < nItems; it += 64) {
            DItem im = sIt[it];                  // LDS.128 (1 wavefront per warp)
            ull a0 = 0ull, a1 = 0ull;
            const int base = (int)im.yAdd + c4;
            const int ts = im.termStart, tc = im.termCount;   // tc even, ts even
            for (int q = 0; q < tc; q += 2) {
                ulonglong2 tp = *(const ulonglong2*)&sT[ts + q];   // LDS.128: 2 terms
                unsigned cb0 = (unsigned)tp.x; int yo0 = (int)(tp.x >> 32);
                unsigned cb1 = (unsigned)tp.y; int yo1 = (int)(tp.y >> 32);
                ull cc0, cc1;
                asm("mov.b64 %0, {%1,%1};" : "=l"(cc0) : "r"(cb0));
                asm("mov.b64 %0, {%1,%1};" : "=l"(cc1) : "r"(cb1));
                ulonglong2 yv0 = *(const ulonglong2*)&sY[yo0 + base];   // LDS.128
                ulonglong2 yv1 = *(const ulonglong2*)&sY[yo1 + base];   // LDS.128
                asm("fma.rn.f32x2 %0, %1, %2, %0;" : "+l"(a0) : "l"(cc0), "l"(yv0.x));
                asm("fma.rn.f32x2 %0, %1, %2, %0;" : "+l"(a1) : "l"(cc0), "l"(yv0.y));
                asm("fma.rn.f32x2 %0, %1, %2, %0;" : "+l"(a0) : "l"(cc1), "l"(yv1.x));
                asm("fma.rn.f32x2 %0, %1, %2, %0;" : "+l"(a1) : "l"(cc1), "l"(yv1.y));
            }
            ulonglong2 o; o.x = a0; o.y = a1;
            *(ulonglong2*)&out[(size_t)im.outConst + (size_t)bv * (size_t)im.bvStride + c4] = o;  // STG.128
        }
    }
}

// ===================== host: CG tables + layout metadata =====================

static double factd(int n) {
    static const double f[13] = {1,1,2,6,24,120,720,5040,40320,362880,3628800,39916800,479001600};
    return f[n];
}
static inline int imax3(int a,int b,int c){ int m=a>b?a:b; return m>c?m:c; }
static inline int imin3(int a,int b,int c){ int m=a<b?a:b; return m<c?m:c; }

static double su2cg(int j1,int m1,int j2,int m2,int j3,int m3) {
    if (m3 != m1 + m2) return 0.0;
    int vmin = imax3(-j1 + j2 + m3, -j1 + m1, 0);
    int vmax = imin3(j2 + j3 + m1, j3 - j1 + j2, j3 + m3);
    double C = sqrt((2*j3+1) * factd(j3+j1-j2) * factd(j3-j1+j2) * factd(j1+j2-j3)
                    * factd(j3+m3) * factd(j3-m3)
                    / (factd(j1+j2+j3+1) * factd(j1-m1) * factd(j1+m1)
                       * factd(j2-m2) * factd(j2+m2)));
    double S = 0.0;
    for (int v = vmin; v <= vmax; v++) {
        double term = factd(j2+j3+m1-v) * factd(j1-m1+v)
                    / (factd(v) * factd(j3-j1+j2-v) * factd(j3+m3-v) * factd(v+j1-j2-m3));
        S += (((v + j2 + m2) & 1) ? -1.0 : 1.0) * term;
    }
    return C * S;
}

struct HC { double re, im; };
static inline HC cmul(HC a, HC b){ HC r; r.re=a.re*b.re-a.im*b.im; r.im=a.re*b.im+a.im*b.re; return r; }

static void qmat(int l, HC q[7][7]) {
    memset(q, 0, sizeof(HC)*49);
    double s2 = 1.0 / sqrt(2.0);
    for (int m = -l; m < 0; m++) {
        q[l+m][l-m].re = s2;
        q[l+m][l+m].im = -s2;
    }
    q[l][l].re = 1.0;
    for (int m = 1; m <= l; m++) {
        double s = (m & 1) ? -1.0 : 1.0;
        q[l+m][l+m].re = s * s2;
        q[l+m][l-m].im = s * s2;
    }
    HC ph; int lm = l & 3;              // (-i)^l
    if      (lm == 0) { ph.re = 1;  ph.im = 0; }
    else if (lm == 1) { ph.re = 0;  ph.im = -1; }
    else if (lm == 2) { ph.re = -1; ph.im = 0; }
    else              { ph.re = 0;  ph.im = 1; }
    for (int a = 0; a < 2*l+1; a++)
        for (int b = 0; b < 2*l+1; b++)
            q[a][b] = cmul(q[a][b], ph);
}

// real CG table C[n][m][p], shapes (2j+1, 2l+1, 2J+1)
static void realcg(int j, int l, int J, double C[7][7][7]) {
    double Ct[7][7][7];
    memset(Ct, 0, sizeof(Ct));
    for (int m1 = -j; m1 <= j; m1++)
        for (int m2 = -l; m2 <= l; m2++) {
            int m3 = m1 + m2;
            if (m3 >= -J && m3 <= J)
                Ct[j+m1][l+m2][J+m3] = su2cg(j, m1, l, m2, J, m3);
        }
    HC Q1[7][7], Q2[7][7], Q3[7][7];
    qmat(j, Q1); qmat(l, Q2); qmat(J, Q3);
    int d1 = 2*j+1, d2 = 2*l+1, d3 = 2*J+1;
    memset(C, 0, sizeof(double)*343);
    for (int jj = 0; jj < d1; jj++)
    for (int ll = 0; ll < d2; ll++)
    for (int mm = 0; mm < d3; mm++) {
        double sre = 0.0;
        for (int i = 0; i < d1; i++) {
            HC a = Q1[i][jj]; if (a.re == 0.0 && a.im == 0.0) continue;
            for (int k = 0; k < d2; k++) {
                HC b = Q2[k][ll]; if (b.re == 0.0 && b.im == 0.0) continue;
                HC ab = cmul(a, b);
                for (int n = 0; n < d3; n++) {
                    double cv = Ct[i][k][n]; if (cv == 0.0) continue;
                    HC c3; c3.re = Q3[n][mm].re; c3.im = -Q3[n][mm].im;  // conj
                    HC tt = cmul(ab, c3);
                    sre += tt.re * cv;
                }
            }
        }
        C[jj][ll][mm] = sre;
    }
}

static DItem g_items[MAX_ITEMS];
static ull   g_terms[MAX_TERMS];
static int   g_nItems = 0;
static bool  g_built = false;

static const int y_off_h[5] = {0,4,13,23,30};
static const int c_off_h[5] = {0,16,64,144,256};
static const int W_h[4]     = {160,336,384,320};
static const long long secOff_h[4] = {0, 1310720, 9568256, 25296896};
static const int secStride_h[4]    = {160, 1008, 1920, 2240};

static void push_item(int &nI, int outConst, int J, int ts, int tc, int yAdd) {
    if (nI < MAX_ITEMS) {
        DItem &im = g_items[nI];
        im.outConst  = outConst;
        im.bvStride  = (us)secStride_h[J];
        im.termStart = (us)ts;
        im.termCount = (us)tc;
        im.yAdd      = (us)yAdd;
        im.pad       = 0;
    }
    nI++;
}
static void push_term(int &nT, double c, int y) {
    if (nT < MAX_TERMS) {
        float cf = (float)c;
        unsigned cb; memcpy(&cb, &cf, 4);
        g_terms[nT] = ((ull)(unsigned)y << 32) | cb;   // y high, coeff low
    }
    nT++;
}
// pad current list (started at ts) to even length with a zero term (coeff 0, yoff 0)
static void pad_even(int &nT, int ts) {
    if ((nT - ts) & 1) push_term(nT, 0.0, 0);
}

static void build_meta() {
    int nI = 0, nT = 0;
    int chCur[4] = {0,0,0,0};
    memset(g_terms, 0, sizeof(g_terms));
    memset(g_items, 0, sizeof(g_items));

    // 1) direct l=0 blocks: first block of each out[j]
    for (int j = 0; j <= 3; j++) {
        int f = 4-j, w = f*16;
        int chOff = chCur[j]; chCur[j] += w;
        for (int p = 0; p <= 2*j; p++) {
            int ts = nT;
            push_term(nT, 1.0, (y_off_h[j] + p*f) * YSTR);   // col 0 (l=0, m=0)
            pad_even(nT, ts);
            int tc = nT - ts;
            for (int r = 0; r < f; r++)
                push_item(nI, (int)secOff_h[j] + p*W_h[j] + chOff + r*16, j, ts, tc, r*YSTR);
        }
    }
    // 2) direct j=0 blocks: second block of out[l], l=1..3
    for (int l = 1; l <= 3; l++) {
        int chOff = chCur[l]; chCur[l] += 64;
        for (int p = 0; p <= 2*l; p++) {
            int ts = nT;
            push_term(nT, 1.0, c_off_h[l] + p*16);           // y row = r via yAdd
            pad_even(nT, ts);
            int tc = nT - ts;
            for (int r = 0; r < 4; r++)
                push_item(nI, (int)secOff_h[l] + p*W_h[l] + chOff + r*16, l, ts, tc, r*YSTR);
        }
    }
    // 3) CG blocks, reference order: l outer, j inner, J ascending
    for (int l = 1; l <= 3; l++)
        for (int j = 1; j <= 3; j++) {
            int lo = (j > l) ? j - l : l - j;
            int hi = (j + l > 3) ? 3 : j + l;
            for (int J = lo; J <= hi; J++) {
                double C[7][7][7];
                realcg(j, l, J, C);
                int f = 4-j, w = f*16;
                int chOff = chCur[J]; chCur[J] += w;
                for (int p = 0; p <= 2*J; p++) {
                    int ts = nT;
                    for (int n = 0; n <= 2*j; n++)
                        for (int m = 0; m <= 2*l; m++) {
                            double c = C[n][m][p];
                            if (fabs(c) > 1e-8)
                                push_term(nT, c, (y_off_h[j] + n*f) * YSTR + c_off_h[l] + m*16);
                        }
                    pad_even(nT, ts);
                    int tc = nT - ts;
                    for (int r = 0; r < f; r++)
                        push_item(nI, (int)(secOff_h[J] + p*W_h[J] + chOff + r*16), J, ts, tc, r*YSTR);
                }
            }
        }
    g_nItems = (nI <= MAX_ITEMS) ? nI : MAX_ITEMS;

    // Stable insertion sort: termCount descending (warp-iteration balance).
    for (int i = 1; i < g_nItems; i++) {
        DItem key = g_items[i];
        int k = i - 1;
        while (k >= 0 && g_items[k].termCount < key.termCount) {
            g_items[k+1] = g_items[k];
            k--;
        }
        g_items[k+1] = key;
    }
}

// ===================== entry point =====================

extern "C" void kernel_launch(void* const* d_in, const int* in_sizes, int n_in,
                              void* d_out, int out_size) {
    if (!g_built) {
        build_meta();
        cudaMemcpyToSymbol(gTerms, g_terms, sizeof(g_terms));   // pre-capture, one-time
        cudaMemcpyToSymbol(gItems, g_items, sizeof(g_items));
        cudaFuncSetAttribute(shconv_kernel,
                             cudaFuncAttributeMaxDynamicSharedMemorySize, SMEM_BYTES);
        g_built = true;
    }
    shconv_kernel<<<8192, 256, SMEM_BYTES>>>(
        g_nItems,
        (const float*)d_in[0], (const float*)d_in[1],
        (const float*)d_in[2], (const float*)d_in[3],
        (const int*)d_in[4],   (const float*)d_in[5],
        (float*)d_out);
}

// round 17
// speedup vs baseline: 1.1634x; 1.1634x over previous
#include <cuda_runtime.h>
#include <math.h>
#include <string.h>

typedef unsigned long long ull;
typedef unsigned short us;

#define GSTR 256            // gathered row stride (floats)
#define YSTR 264            // y row stride (floats)
#define UNION_FLOATS (32*YSTR)   // 8448 floats = 33792 B  (>= 32*GSTR)
#define MAX_ITEMS 336
#define MAX_TERMS 1536      // term table bound (actual ~1.3K)
#define BV_PER_BLK 2

// 16-byte item record (LDS.128-friendly)
struct __align__(16) DItem { int outConst; us bvStride, termStart, termCount, yAdd; us pad; };

__device__ ull   gTerms[MAX_TERMS];     // term = {float c (low 32), int y (high 32)}
__device__ DItem gItems[MAX_ITEMS];

// union(sG,sY) 33792 + sK 4096 + sT 12288 + sItems 5376 = 55552 B -> 4 CTAs/SM (222 KB)
#define SMEM_BYTES (UNION_FLOATS*4 + 32*32*4 + MAX_TERMS*8 + MAX_ITEMS*16)

// ===================== device kernel =====================

__global__ void __launch_bounds__(256, 4) shconv_kernel(
    int nItems,
    const float* __restrict__ x0, const float* __restrict__ x1,
    const float* __restrict__ x2, const float* __restrict__ x3,
    const int*  __restrict__ pidx, const float* __restrict__ kern,
    float* __restrict__ out)
{
    extern __shared__ float smem[];
    float* sG  = smem;                      // [32][GSTR]  (phase 1-2)
    float* sY  = smem;                      // [32][YSTR]  (aliases sG after barrier)
    float* sK  = smem + UNION_FLOATS;       // [32][32]    K, rows 30,31 zero-padded
    ull*   sT  = (ull*)(sK + 1024);         // [MAX_TERMS] term table
    DItem* sIt = (DItem*)(sT + MAX_TERMS);  // [MAX_ITEMS] items

    const int t    = threadIdx.x;
    const int lane = t & 31, w = t >> 5;

    // ---- One-time per block: copy term + item tables into smem ----
    #pragma unroll
    for (int i = 0; i < MAX_TERMS/256; i++)
        sT[t + i*256] = gTerms[t + i*256];
    {
        const ulonglong2* gi = (const ulonglong2*)gItems;
        ulonglong2* si = (ulonglong2*)sIt;
        for (int i = t; i < MAX_ITEMS; i += 256) si[i] = gi[i];
    }

    #pragma unroll 1
    for (int ti = 0; ti < BV_PER_BLK; ti++) {
        const int bv = blockIdx.x * BV_PER_BLK + ti;

        // ---- Phase 0b: load K[32 patches][30 rows], pad rows to 32 ----
        const float* kb = kern + (size_t)bv * (32*30);
        for (int e = t; e < 1024; e += 256) {
            int p = e >> 5, row = e & 31;
            sK[e] = (row < 30) ? __ldg(kb + p*30 + row) : 0.f;
        }

        // ---- Phase 1: gather G[32][256] via cp.async (L2 -> smem) ----
        const int* pb = pidx + (size_t)bv * 64;
        #pragma unroll
        for (int pi = 0; pi < 4; pi++) {
            int p  = w + pi*8;
            int b2 = __ldg(pb + 2*p);
            int n  = __ldg(pb + 2*p + 1);
            size_t bn = (size_t)b2 * 4096 + (size_t)n;
            #pragma unroll
            for (int qq = 0; qq < 2; qq++) {
                int q = lane + qq*32;    // 64 float4 chunks per patch row
                const float* src;
                if (q < 4)       src = x0 + bn*16  + q*4;
                else if (q < 16) src = x1 + bn*48  + (q-4)*4;
                else if (q < 36) src = x2 + bn*80  + (q-16)*4;
                else             src = x3 + bn*112 + (q-36)*4;
                unsigned daddr = (unsigned)__cvta_generic_to_shared(&sG[p*GSTR + q*4]);
                asm volatile("cp.async.cg.shared.global [%0], [%1], 16;\n"
                             :: "r"(daddr), "l"(src));
            }
        }
        asm volatile("cp.async.commit_group;\n");
        asm volatile("cp.async.wait_group 0;\n");
        __syncthreads();

        // ---- Phase 2: y[30][256] = K^T(30x32) @ G(32x256), 8 rows x 64 pairs/warp ----
        {
            const int rg = w >> 1;          // row group: rows rg*8 .. rg*8+7
            const int ph = w & 1;           // pair half
            const int col = (ph*64 + lane)*2;   // float column of first pair
            ull acc[8][2];
            #pragma unroll
            for (int i = 0; i < 8; i++) { acc[i][0] = 0ull; acc[i][1] = 0ull; }

            #pragma unroll 2
            for (int p = 0; p < 32; p++) {
                const float* gr = sG + p*GSTR + col;
                ull g0 = *(const ull*)(gr);
                ull g1 = *(const ull*)(gr + 64);
                float4 ka = *(const float4*)&sK[p*32 + rg*8];       // broadcast LDS.128
                float4 kc = *(const float4*)&sK[p*32 + rg*8 + 4];   // broadcast LDS.128
                ull kd[8];
                asm("mov.b64 %0, {%1,%1};" : "=l"(kd[0]) : "r"(__float_as_uint(ka.x)));
                asm("mov.b64 %0, {%1,%1};" : "=l"(kd[1]) : "r"(__float_as_uint(ka.y)));
                asm("mov.b64 %0, {%1,%1};" : "=l"(kd[2]) : "r"(__float_as_uint(ka.z)));
                asm("mov.b64 %0, {%1,%1};" : "=l"(kd[3]) : "r"(__float_as_uint(ka.w)));
                asm("mov.b64 %0, {%1,%1};" : "=l"(kd[4]) : "r"(__float_as_uint(kc.x)));
                asm("mov.b64 %0, {%1,%1};" : "=l"(kd[5]) : "r"(__float_as_uint(kc.y)));
                asm("mov.b64 %0, {%1,%1};" : "=l"(kd[6]) : "r"(__float_as_uint(kc.z)));
                asm("mov.b64 %0, {%1,%1};" : "=l"(kd[7]) : "r"(__float_as_uint(kc.w)));
                #pragma unroll
                for (int i = 0; i < 8; i++) {
                    asm("fma.rn.f32x2 %0, %1, %2, %0;" : "+l"(acc[i][0]) : "l"(kd[i]), "l"(g0));
                    asm("fma.rn.f32x2 %0, %1, %2, %0;" : "+l"(acc[i][1]) : "l"(kd[i]), "l"(g1));
                }
            }
            // all warps finished reading sG -> safe to overwrite union with y
            __syncthreads();
            #pragma unroll
            for (int i = 0; i < 8; i++) {
                int row = rg*8 + i;
                *(ull*)&sY[row*YSTR + col]      = acc[i][0];
                *(ull*)&sY[row*YSTR + col + 64] = acc[i][1];
            }
        }
        __syncthreads();

        // ---- Phase 3: CG recombination + direct copies, 4 floats/lane (LDS.128) ----
        {
            const int c4  = (t & 3) * 4;    // channels c4..c4+3 (16 per item, 4 lanes/item)
            const int grp = t >> 2;         // 64 item-groups
            for (int it = grp; it < nItems; it += 64) {
                DItem im = sIt[it];                  // LDS.128 (1 wavefront per warp)
                ull a0 = 0ull, a1 = 0ull;
                const int base = (int)im.yAdd + c4;
                const int ts = im.termStart, tc = im.termCount;
                for (int q = 0; q < tc; q++) {
                    ull tm = sT[ts + q];             // term: coeff lo32, yoff hi32
                    unsigned cb = (unsigned)tm;
                    int yoff = (int)(tm >> 32);
                    ull cc;
                    asm("mov.b64 %0, {%1,%1};" : "=l"(cc) : "r"(cb));
                    ulonglong2 yv = *(const ulonglong2*)&sY[yoff + base];   // LDS.128
                    asm("fma.rn.f32x2 %0, %1, %2, %0;" : "+l"(a0) : "l"(cc), "l"(yv.x));
                    asm("fma.rn.f32x2 %0, %1, %2, %0;" : "+l"(a1) : "l"(cc), "l"(yv.y));
                }
                ulonglong2 o; o.x = a0; o.y = a1;
                *(ulonglong2*)&out[(size_t)im.outConst + (size_t)bv * (size_t)im.bvStride + c4] = o;  // STG.128
            }
        }
        // phase-3 sY reads must finish before next tile's gather overwrites sG
        __syncthreads();
    }
}

// ===================== host: CG tables + layout metadata =====================

static double factd(int n) {
    static const double f[13] = {1,1,2,6,24,120,720,5040,40320,362880,3628800,39916800,479001600};
    return f[n];
}
static inline int imax3(int a,int b,int c){ int m=a>b?a:b; return m>c?m:c; }
static inline int imin3(int a,int b,int c){ int m=a<b?a:b; return m<c?m:c; }

static double su2cg(int j1,int m1,int j2,int m2,int j3,int m3) {
    if (m3 != m1 + m2) return 0.0;
    int vmin = imax3(-j1 + j2 + m3, -j1 + m1, 0);
    int vmax = imin3(j2 + j3 + m1, j3 - j1 + j2, j3 + m3);
    double C = sqrt((2*j3+1) * factd(j3+j1-j2) * factd(j3-j1+j2) * factd(j1+j2-j3)
                    * factd(j3+m3) * factd(j3-m3)
                    / (factd(j1+j2+j3+1) * factd(j1-m1) * factd(j1+m1)
                       * factd(j2-m2) * factd(j2+m2)));
    double S = 0.0;
    for (int v = vmin; v <= vmax; v++) {
        double term = factd(j2+j3+m1-v) * factd(j1-m1+v)
                    / (factd(v) * factd(j3-j1+j2-v) * factd(j3+m3-v) * factd(v+j1-j2-m3));
        S += (((v + j2 + m2) & 1) ? -1.0 : 1.0) * term;
    }
    return C * S;
}

struct HC { double re, im; };
static inline HC cmul(HC a, HC b){ HC r; r.re=a.re*b.re-a.im*b.im; r.im=a.re*b.im+a.im*b.re; return r; }

static void qmat(int l, HC q[7][7]) {
    memset(q, 0, sizeof(HC)*49);
    double s2 = 1.0 / sqrt(2.0);
    for (int m = -l; m < 0; m++) {
        q[l+m][l-m].re = s2;
        q[l+m][l+m].im = -s2;
    }
    q[l][l].re = 1.0;
    for (int m = 1; m <= l; m++) {
        double s = (m & 1) ? -1.0 : 1.0;
        q[l+m][l+m].re = s * s2;
        q[l+m][l-m].im = s * s2;
    }
    HC ph; int lm = l & 3;              // (-i)^l
    if      (lm == 0) { ph.re = 1;  ph.im = 0; }
    else if (lm == 1) { ph.re = 0;  ph.im = -1; }
    else if (lm == 2) { ph.re = -1; ph.im = 0; }
    else              { ph.re = 0;  ph.im = 1; }
    for (int a = 0; a < 2*l+1; a++)
        for (int b = 0; b < 2*l+1; b++)
            q[a][b] = cmul(q[a][b], ph);
}

// real CG table C[n][m][p], shapes (2j+1, 2l+1, 2J+1)
static void realcg(int j, int l, int J, double C[7][7][7]) {
    double Ct[7][7][7];
    memset(Ct, 0, sizeof(Ct));
    for (int m1 = -j; m1 <= j; m1++)
        for (int m2 = -l; m2 <= l; m2++) {
            int m3 = m1 + m2;
            if (m3 >= -J && m3 <= J)
                Ct[j+m1][l+m2][J+m3] = su2cg(j, m1, l, m2, J, m3);
        }
    HC Q1[7][7], Q2[7][7], Q3[7][7];
    qmat(j, Q1); qmat(l, Q2); qmat(J, Q3);
    int d1 = 2*j+1, d2 = 2*l+1, d3 = 2*J+1;
    memset(C, 0, sizeof(double)*343);
    for (int jj = 0; jj < d1; jj++)
    for (int ll = 0; ll < d2; ll++)
    for (int mm = 0; mm < d3; mm++) {
        double sre = 0.0;
        for (int i = 0; i < d1; i++) {
            HC a = Q1[i][jj]; if (a.re == 0.0 && a.im == 0.0) continue;
            for (int k = 0; k < d2; k++) {
                HC b = Q2[k][ll]; if (b.re == 0.0 && b.im == 0.0) continue;
                HC ab = cmul(a, b);
                for (int n = 0; n < d3; n++) {
                    double cv = Ct[i][k][n]; if (cv == 0.0) continue;
                    HC c3; c3.re = Q3[n][mm].re; c3.im = -Q3[n][mm].im;  // conj
                    HC tt = cmul(ab, c3);
                    sre += tt.re * cv;
                }
            }
        }
        C[jj][ll][mm] = sre;
    }
}

static DItem g_items[MAX_ITEMS];
static ull   g_terms[MAX_TERMS];
static int   g_nItems = 0;
static bool  g_built = false;

static const int y_off_h[5] = {0,4,13,23,30};
static const int c_off_h[5] = {0,16,64,144,256};
static const int W_h[4]     = {160,336,384,320};
static const long long secOff_h[4] = {0, 1310720, 9568256, 25296896};
static const int secStride_h[4]    = {160, 1008, 1920, 2240};

static void push_item(int &nI, int outConst, int J, int ts, int tc, int yAdd) {
    if (nI < MAX_ITEMS) {
        DItem &im = g_items[nI];
        im.outConst  = outConst;
        im.bvStride  = (us)secStride_h[J];
        im.termStart = (us)ts;
        im.termCount = (us)tc;
        im.yAdd      = (us)yAdd;
        im.pad       = 0;
    }
    nI++;
}
static void push_term(int &nT, double c, int y) {
    if (nT < MAX_TERMS) {
        float cf = (float)c;
        unsigned cb; memcpy(&cb, &cf, 4);
        g_terms[nT] = ((ull)(unsigned)y << 32) | cb;   // y high, coeff low
    }
    nT++;
}

static void build_meta() {
    int nI = 0, nT = 0;
    int chCur[4] = {0,0,0,0};
    memset(g_terms, 0, sizeof(g_terms));
    memset(g_items, 0, sizeof(g_items));

    // 1) direct l=0 blocks: first block of each out[j]
    for (int j = 0; j <= 3; j++) {
        int f = 4-j, w = f*16;
        int chOff = chCur[j]; chCur[j] += w;
        for (int p = 0; p <= 2*j; p++) {
            int ts = nT;
            push_term(nT, 1.0, (y_off_h[j] + p*f) * YSTR);   // col 0 (l=0, m=0)
            for (int r = 0; r < f; r++)
                push_item(nI, (int)secOff_h[j] + p*W_h[j] + chOff + r*16, j, ts, 1, r*YSTR);
        }
    }
    // 2) direct j=0 blocks: second block of out[l], l=1..3
    for (int l = 1; l <= 3; l++) {
        int chOff = chCur[l]; chCur[l] += 64;
        for (int p = 0; p <= 2*l; p++) {
            int ts = nT;
            push_term(nT, 1.0, c_off_h[l] + p*16);           // y row = r via yAdd
            for (int r = 0; r < 4; r++)
                push_item(nI, (int)secOff_h[l] + p*W_h[l] + chOff + r*16, l, ts, 1, r*YSTR);
        }
    }
    // 3) CG blocks, reference order: l outer, j inner, J ascending
    for (int l = 1; l <= 3; l++)
        for (int j = 1; j <= 3; j++) {
            int lo = (j > l) ? j - l : l - j;
            int hi = (j + l > 3) ? 3 : j + l;
            for (int J = lo; J <= hi; J++) {
                double C[7][7][7];
                realcg(j, l, J, C);
                int f = 4-j, w = f*16;
                int chOff = chCur[J]; chCur[J] += w;
                for (int p = 0; p <= 2*J; p++) {
                    int ts = nT;
                    for (int n = 0; n <= 2*j; n++)
                        for (int m = 0; m <= 2*l; m++) {
                            double c = C[n][m][p];
                            if (fabs(c) > 1e-8)
                                push_term(nT, c, (y_off_h[j] + n*f) * YSTR + c_off_h[l] + m*16);
                        }
                    int tc = nT - ts;
                    for (int r = 0; r < f; r++)
                        push_item(nI, (int)(secOff_h[J] + p*W_h[J] + chOff + r*16), J, ts, tc, r*YSTR);
                }
            }
        }
    g_nItems = (nI <= MAX_ITEMS) ? nI : MAX_ITEMS;

    // Stable insertion sort: termCount descending (warp-iteration balance).
    for (int i = 1; i < g_nItems; i++) {
        DItem key = g_items[i];
        int k = i - 1;
        while (k >= 0 && g_items[k].termCount < key.termCount) {
            g_items[k+1] = g_items[k];
            k--;
        }
        g_items[k+1] = key;
    }
}

// ===================== entry point =====================

extern "C" void kernel_launch(void* const* d_in, const int* in_sizes, int n_in,
                              void* d_out, int out_size) {
    if (!g_built) {
        build_meta();
        cudaMemcpyToSymbol(gTerms, g_terms, sizeof(g_terms));   // pre-capture, one-time
        cudaMemcpyToSymbol(gItems, g_items, sizeof(g_items));
        cudaFuncSetAttribute(shconv_kernel,
                             cudaFuncAttributeMaxDynamicSharedMemorySize, SMEM_BYTES);
        g_built = true;
    }
    shconv_kernel<<<8192/BV_PER_BLK, 256, SMEM_BYTES>>>(
        g_nItems,
        (const float*)d_in[0], (const float*)d_in[1],
        (const float*)d_in[2], (const float*)d_in[3],
        (const int*)d_in[4],   (const float*)d_in[5],
        (float*)d_out);
}